// round 12
// baseline (speedup 1.0000x reference)
#include <cuda_runtime.h>
#include <cuda_fp16.h>
#include <math.h>
#include <stdint.h>

#define BB 2
#define NN 2048
#define CC 1024
#define HH 16
#define DD 64

// ---- scratch (device globals; allocation-free per harness rules) ----
__device__ float  g_q [BB*HH*NN*DD];          // fp32 q (pre-LN)
__device__ float  g_k [BB*HH*NN*DD];          // fp32 k (pre-LN)
__device__ __half g_qh[BB*HH*NN*DD], g_ql[BB*HH*NN*DD];   // post-LN fp16 hi/lo
__device__ __half g_kh[BB*HH*NN*DD], g_kl[BB*HH*NN*DD];
__device__ __half g_vh[BB*HH*NN*DD], g_vl[BB*HH*NN*DD];
__device__ __half g_aoh[BB*NN*CC],  g_aol[BB*NN*CC];      // attn out hi/lo
__device__ __half g_xh[BB*NN*CC],   g_xl[BB*NN*CC];       // x hi/lo
__device__ __half g_wqh[CC*3*CC],   g_wql[CC*3*CC];       // w_qkv hi/lo
__device__ __half g_wph[CC*CC],     g_wpl[CC*CC];         // w_proj hi/lo

// ===========================================================================
// helpers
// ===========================================================================
__device__ __forceinline__ void mma16816(float* d, const uint32_t* a,
                                         uint32_t b0, uint32_t b1) {
    asm volatile(
        "mma.sync.aligned.m16n8k16.row.col.f32.f16.f16.f32 "
        "{%0,%1,%2,%3}, {%4,%5,%6,%7}, {%8,%9}, {%0,%1,%2,%3};"
        : "+f"(d[0]), "+f"(d[1]), "+f"(d[2]), "+f"(d[3])
        : "r"(a[0]), "r"(a[1]), "r"(a[2]), "r"(a[3]), "r"(b0), "r"(b1));
}
__device__ __forceinline__ uint32_t smem_u32(const void* p) {
    uint32_t a;
    asm("{ .reg .u64 t; cvta.to.shared.u64 t, %1; cvt.u32.u64 %0, t; }"
        : "=r"(a) : "l"(p));
    return a;
}
__device__ __forceinline__ float ex2f(float x) {
    float r;
    asm("ex2.approx.f32 %0, %1;" : "=f"(r) : "f"(x));
    return r;
}
#define LDSM_X4(r0, r1, r2, r3, addr) \
    asm volatile("ldmatrix.sync.aligned.m8n8.x4.shared.b16 " \
                 "{%0,%1,%2,%3}, [%4];" \
                 : "=r"(r0), "=r"(r1), "=r"(r2), "=r"(r3) : "r"(addr))
#define LDSM_X4_T(r0, r1, r2, r3, addr) \
    asm volatile("ldmatrix.sync.aligned.m8n8.x4.trans.shared.b16 " \
                 "{%0,%1,%2,%3}, [%4];" \
                 : "=r"(r0), "=r"(r1), "=r"(r2), "=r"(r3) : "r"(addr))
#define CPA16(dst, src) \
    asm volatile("cp.async.cg.shared.global [%0], [%1], 16;" :: "r"(dst), "l"(src))
#define CPA_COMMIT() asm volatile("cp.async.commit_group;" ::)
#define CPA_WAIT(n)  asm volatile("cp.async.wait_group %0;" :: "n"(n))

// split (a,b) into fp16 hi pair + fp16 residual pair
__device__ __forceinline__ void splitp(float a, float b, uint32_t& hi, uint32_t& lo) {
    __half2 h = __floats2half2_rn(a, b);
    float2 f = __half22float2(h);
    __half2 l = __floats2half2_rn(a - f.x, b - f.y);
    hi = *(uint32_t*)&h;
    lo = *(uint32_t*)&l;
}
__device__ __forceinline__ void split8(float4 v, uint2& hi, uint2& lo) {
    splitp(v.x, v.y, hi.x, lo.x);
    splitp(v.z, v.w, hi.y, lo.y);
}

// ===========================================================================
// fp32 -> fp16 hi/lo streaming conversion
// ===========================================================================
__global__ __launch_bounds__(256)
void f2h_split(const float* __restrict__ src, __half* __restrict__ hi,
               __half* __restrict__ lo, int n4)
{
    int i = blockIdx.x * blockDim.x + threadIdx.x;
    if (i >= n4) return;
    float4 v = ((const float4*)src)[i];
    uint2 h, l;
    split8(v, h, l);
    ((uint2*)hi)[i] = h;
    ((uint2*)lo)[i] = l;
}

// ===========================================================================
// fp16 3-term GEMM:  CTA 256x128, 512 threads (4x4 warps, 64x32/warp),
// BK=32 cp.async double-buffer, ONE sync per chunk (192 MMAs between syncs).
// MODE 0: A=x, W=w_qkv (Nn=3072) -> q/k fp32 + v fp16 hi/lo
// MODE 1: A=ao hi/lo, W=w_proj (Nn=1024), +bias -> Cout fp32
// ===========================================================================
#define ASTR 40                        // A smem stride (halves)
#define BSTR 136                       // B smem stride (halves)
#define OAL  (256 * ASTR)              // 10240: A-lo offset (halves)
#define OBH  (2 * 256 * ASTR)          // 20480
#define OBL  (OBH + 32 * BSTR)         // 24832
#define STGH (OBH + 2 * 32 * BSTR)     // 29184 halves / stage
#define STGB (STGH * 2)                // 58368 B
#define GEMM_SMEM (2 * STGB)           // 116736 B

template<int MODE>
__global__ __launch_bounds__(512, 1)
void tc_gemm(const float* __restrict__ bias, float* __restrict__ Cout)
{
    constexpr int K  = 1024;
    constexpr int NC = K / 32;                    // 32 chunks
    constexpr int Nn = (MODE == 0) ? 3072 : 1024;

    const __half* Agh = (MODE == 0) ? g_xh  : g_aoh;
    const __half* Agl = (MODE == 0) ? g_xl  : g_aol;
    const __half* Bgh = (MODE == 0) ? g_wqh : g_wph;
    const __half* Bgl = (MODE == 0) ? g_wql : g_wpl;

    extern __shared__ __half smh[];
    const uint32_t smb = smem_u32(smh);

    const int tid  = threadIdx.x;
    const int wid  = tid >> 5, lane = tid & 31;
    const int wm   = wid & 3,  wn   = wid >> 2;    // 4(m) x 4(n)
    const int g    = lane >> 2, tig = lane & 3;
    const int rowg0 = blockIdx.y * 256;
    const int nblk  = blockIdx.x * 128;

    auto issue = [&](int c, int st) {
        const uint32_t sb = smb + st * STGB;
        #pragma unroll
        for (int s = 0; s < 4; ++s) {             // A: 2048 16B chunks
            int idx = tid + s * 512;
            int arr = idx >> 10, rem = idx & 1023;
            int row = rem >> 2, ch = rem & 3;
            const __half* gp = (arr ? Agl : Agh)
                + (size_t)(rowg0 + row) * K + c * 32 + ch * 8;
            CPA16(sb + ((arr ? OAL : 0) + row * ASTR + ch * 8) * 2, gp);
        }
        #pragma unroll
        for (int s = 0; s < 2; ++s) {             // B: 1024 16B chunks
            int idx = tid + s * 512;
            int arr = idx >> 9, rem = idx & 511;
            int rr = rem >> 4, ch = rem & 15;
            const __half* gp = (arr ? Bgl : Bgh)
                + (size_t)(c * 32 + rr) * Nn + nblk + ch * 8;
            CPA16(sb + ((arr ? OBL : OBH) + rr * BSTR + ch * 8) * 2, gp);
        }
    };

    float acc[4][4][4];
    #pragma unroll
    for (int i = 0; i < 4; ++i)
        #pragma unroll
        for (int j = 0; j < 4; ++j)
            #pragma unroll
            for (int r = 0; r < 4; ++r) acc[i][j][r] = 0.0f;

    issue(0, 0);
    CPA_COMMIT();

    const int lrow = lane & 15, lch = (lane >> 4) << 3;
    const int brow = ((lane >> 3) & 1) * 8 + (lane & 7);

    for (int c = 0; c < NC; ++c) {
        CPA_WAIT(0);
        __syncthreads();                 // chunk c ready; other slot free
        if (c + 1 < NC) {
            issue(c + 1, (c + 1) & 1);
            CPA_COMMIT();
        }

        const int st = c & 1;
        const __half* Ah = smh + st * STGH;
        const __half* Al = Ah + OAL;
        const __half* Bh = smh + st * STGH + OBH;
        const __half* Bl = smh + st * STGH + OBL;

        #pragma unroll
        for (int ks = 0; ks < 2; ++ks) {
            uint32_t afh[4][4], afl[4][4], bfh[4][2], bfl[4][2];
            #pragma unroll
            for (int s = 0; s < 4; ++s) {
                const int m0 = wm * 64 + s * 16;
                LDSM_X4(afh[s][0], afh[s][1], afh[s][2], afh[s][3],
                        smem_u32(Ah + (m0 + lrow) * ASTR + ks * 16 + lch));
                LDSM_X4(afl[s][0], afl[s][1], afl[s][2], afl[s][3],
                        smem_u32(Al + (m0 + lrow) * ASTR + ks * 16 + lch));
            }
            #pragma unroll
            for (int np = 0; np < 2; ++np) {
                const int n0 = wn * 32 + np * 16;
                LDSM_X4_T(bfh[2*np][0], bfh[2*np][1], bfh[2*np+1][0], bfh[2*np+1][1],
                          smem_u32(Bh + (ks * 16 + brow) * BSTR + n0 + lch));
                LDSM_X4_T(bfl[2*np][0], bfl[2*np][1], bfl[2*np+1][0], bfl[2*np+1][1],
                          smem_u32(Bl + (ks * 16 + brow) * BSTR + n0 + lch));
            }
            #pragma unroll
            for (int i = 0; i < 4; ++i)
                #pragma unroll
                for (int j = 0; j < 4; ++j) {
                    mma16816(acc[i][j], afl[i], bfh[j][0], bfh[j][1]);
                    mma16816(acc[i][j], afh[i], bfl[j][0], bfl[j][1]);
                    mma16816(acc[i][j], afh[i], bfh[j][0], bfh[j][1]);
                }
        }
    }

    // ---- epilogue ----
    #pragma unroll
    for (int i = 0; i < 4; ++i) {
        const int r1 = rowg0 + wm * 64 + i * 16 + g;
        #pragma unroll
        for (int j = 0; j < 4; ++j) {
            const int cgl = nblk + wn * 32 + j * 8 + tig * 2;
            if (MODE == 0) {
                const int which = cgl >> 10;
                const int head  = (cgl >> 6) & 15;
                const int dd    = cgl & 63;
                #pragma unroll
                for (int h2 = 0; h2 < 2; ++h2) {
                    const int r = r1 + h2 * 8;
                    const int b = r >> 11, n = r & 2047;
                    const size_t off = ((size_t)(b * HH + head) * NN + n) * DD + dd;
                    float a0 = acc[i][j][h2 * 2], a1 = acc[i][j][h2 * 2 + 1];
                    if (which == 0)      *(float2*)(g_q + off) = make_float2(a0, a1);
                    else if (which == 1) *(float2*)(g_k + off) = make_float2(a0, a1);
                    else {
                        uint32_t hi, lo;
                        splitp(a0, a1, hi, lo);
                        *(uint32_t*)(g_vh + off) = hi;
                        *(uint32_t*)(g_vl + off) = lo;
                    }
                }
            } else {
                const float2 bv = *(const float2*)(bias + cgl);
                #pragma unroll
                for (int h2 = 0; h2 < 2; ++h2) {
                    const int r = r1 + h2 * 8;
                    *(float2*)(Cout + (size_t)r * Nn + cgl) =
                        make_float2(acc[i][j][h2 * 2] + bv.x,
                                    acc[i][j][h2 * 2 + 1] + bv.y);
                }
            }
        }
    }
}

// ===========================================================================
// Per-head LayerNorm (D=64) on q,k.  q additionally scaled by sqrt(D)*log2(e)
// so flash softmax can use raw ex2 (base-2 domain).  fp16 hi/lo output.
// ===========================================================================
#define QSCALE 11.5415603271117f       // 8 * log2(e)

__global__ __launch_bounds__(128)
void qk_ln_kernel(const float* __restrict__ ln_w, const float* __restrict__ ln_b)
{
    const int R = BB * HH * NN;
    int row  = blockIdx.x * 4 + (threadIdx.x >> 5);
    int lane = threadIdx.x & 31;

    const bool isq = (row < R);
    const float* src = isq ? g_q : g_k;
    __half* dh = isq ? g_qh : g_kh;
    __half* dl = isq ? g_ql : g_kl;
    float extra = isq ? QSCALE : 1.0f;
    int r = isq ? row : (row - R);

    const float* p = src + (size_t)r * DD;
    float x0 = p[lane];
    float x1 = p[lane + 32];
    float s  = x0 + x1;
    float ss = x0 * x0 + x1 * x1;
    #pragma unroll
    for (int o = 16; o > 0; o >>= 1) {
        s  += __shfl_xor_sync(0xffffffffu, s,  o);
        ss += __shfl_xor_sync(0xffffffffu, ss, o);
    }
    float mu  = s * (1.0f / 64.0f);
    float var = ss * (1.0f / 64.0f) - mu * mu;
    float inv = rsqrtf(var + 1e-5f);
    float y0 = ((x0 - mu) * inv * ln_w[lane]      + ln_b[lane])      * extra;
    float y1 = ((x1 - mu) * inv * ln_w[lane + 32] + ln_b[lane + 32]) * extra;

    __half h0 = __float2half_rn(y0);
    __half h1 = __float2half_rn(y1);
    size_t off = (size_t)r * DD + lane;
    dh[off]      = h0;
    dh[off + 32] = h1;
    dl[off]      = __float2half_rn(y0 - __half2float(h0));
    dl[off + 32] = __float2half_rn(y1 - __half2float(h1));
}

// ===========================================================================
// Tensor-core causal flash attention, pre-split fp16, cp.async double-buffer,
// ONE sync per key tile, base-2 softmax (single ex2.approx per score).
// CTA: 128 q-rows; 8 warps x 16 rows; key tile 64.
// ===========================================================================
#define FSTR 72                         // smem row stride (halves)
#define ARRB (64 * FSTR * 2)            // 9216 B per array
#define BUFB (4 * ARRB)                 // 36864 B per KV buffer
#define FL_SMEM (2 * BUFB)              // 73728 B

__global__ __launch_bounds__(256)
void flash_mma()
{
    extern __shared__ __align__(1024) char fsm[];
    const uint32_t fsmb = smem_u32(fsm);

    const int bh  = blockIdx.y;
    const int qi  = (gridDim.x - 1) - blockIdx.x;   // heavy tiles first
    const int tid = threadIdx.x;
    const int wid = tid >> 5, lane = tid & 31;
    const int g   = lane >> 2, tig = lane & 3;

    const size_t hb = (size_t)bh * NN * DD;
    const size_t qb = hb + (size_t)qi * 128 * DD;

    // ---- stage Q hi/lo into smem, extract per-warp a-frags ----
    {
        __half* Qh = (__half*)fsm;
        __half* Ql = (__half*)(fsm + 18432);
        #pragma unroll
        for (int s = 0; s < 4; ++s) {
            int idx = tid + s * 256;
            int row = idx >> 3, ch = idx & 7;
            *(uint4*)&Qh[row * FSTR + ch * 8] = *(const uint4*)(g_qh + qb + row * 64 + ch * 8);
            *(uint4*)&Ql[row * FSTR + ch * 8] = *(const uint4*)(g_ql + qb + row * 64 + ch * 8);
        }
    }
    __syncthreads();

    uint32_t qh[4][4], ql[4][4];
    {
        const int lr = lane & 15, lc = (lane >> 4) << 3;
        #pragma unroll
        for (int kk = 0; kk < 4; ++kk) {
            uint32_t a = fsmb + ((wid * 16 + lr) * FSTR + kk * 16 + lc) * 2;
            LDSM_X4(qh[kk][0], qh[kk][1], qh[kk][2], qh[kk][3], a);
            LDSM_X4(ql[kk][0], ql[kk][1], ql[kk][2], ql[kk][3], a + 18432);
        }
    }
    __syncthreads();

    auto issueKV = [&](int kj, int b) {
        const size_t kb = hb + (size_t)kj * 64 * DD;
        const uint32_t sb = fsmb + b * BUFB;
        const __half* gs[4] = { g_kh + kb, g_kl + kb, g_vh + kb, g_vl + kb };
        #pragma unroll
        for (int a = 0; a < 4; ++a) {
            const uint32_t so = sb + a * ARRB;
            #pragma unroll
            for (int s = 0; s < 2; ++s) {
                int idx = tid + s * 256;
                int row = idx >> 3, ch = idx & 7;
                CPA16(so + (row * FSTR + ch * 8) * 2, gs[a] + row * 64 + ch * 8);
            }
        }
    };

    float m0 = -1e30f, m1 = -1e30f, l0 = 0.0f, l1 = 0.0f;
    float o[8][4];
    #pragma unroll
    for (int j = 0; j < 8; ++j)
        #pragma unroll
        for (int r = 0; r < 4; ++r) o[j][r] = 0.0f;

    const int lrow = lane & 15, lch = (lane >> 4) << 3;
    const int brow = ((lane >> 3) & 1) * 8 + (lane & 7);
    const int kend = 2 * qi + 1;

    issueKV(0, 0);
    CPA_COMMIT();

    for (int kj = 0; kj <= kend; ++kj) {
        CPA_WAIT(0);
        __syncthreads();                 // tile kj ready; opposite buffer free
        if (kj < kend) {
            issueKV(kj + 1, (kj + 1) & 1);
            CPA_COMMIT();
        }

        const uint32_t bK  = fsmb + (kj & 1) * BUFB;           // K hi
        const uint32_t bKl = bK + ARRB;                        // K lo
        const uint32_t bV  = bK + 2 * ARRB;                    // V hi
        const uint32_t bVl = bK + 3 * ARRB;                    // V lo

        // ---- S = Q K^T (fp16 3-term, non-trans b-frags); base-2 domain ----
        float sf[8][4];
        #pragma unroll
        for (int j = 0; j < 8; ++j)
            #pragma unroll
            for (int r = 0; r < 4; ++r) sf[j][r] = 0.0f;

        #pragma unroll
        for (int kk = 0; kk < 4; ++kk) {
            #pragma unroll
            for (int jp = 0; jp < 4; ++jp) {
                const uint32_t off = ((jp * 16 + lrow) * FSTR + kk * 16 + lch) * 2;
                uint32_t h0, h1, h2, h3, e0, e1, e2, e3;
                LDSM_X4(h0, h1, h2, h3, bK + off);
                LDSM_X4(e0, e1, e2, e3, bKl + off);
                mma16816(sf[2*jp],   ql[kk], h0, h2);
                mma16816(sf[2*jp],   qh[kk], e0, e2);
                mma16816(sf[2*jp],   qh[kk], h0, h2);
                mma16816(sf[2*jp+1], ql[kk], h1, h3);
                mma16816(sf[2*jp+1], qh[kk], e1, e3);
                mma16816(sf[2*jp+1], qh[kk], h1, h3);
            }
        }

        // ---- causal mask on diagonal tiles ----
        if (kj >= 2 * qi) {
            const int row0 = qi * 128 + wid * 16 + g;
            const int row1 = row0 + 8;
            #pragma unroll
            for (int j = 0; j < 8; ++j) {
                const int c0 = kj * 64 + j * 8 + tig * 2;
                if (row0 < c0)     sf[j][0] = -1e30f;
                if (row0 < c0 + 1) sf[j][1] = -1e30f;
                if (row1 < c0)     sf[j][2] = -1e30f;
                if (row1 < c0 + 1) sf[j][3] = -1e30f;
            }
        }

        // ---- online softmax, base-2 (rows g, g+8; quad-replicated) ----
        float mx0 = -1e30f, mx1 = -1e30f;
        #pragma unroll
        for (int j = 0; j < 8; ++j) {
            mx0 = fmaxf(mx0, fmaxf(sf[j][0], sf[j][1]));
            mx1 = fmaxf(mx1, fmaxf(sf[j][2], sf[j][3]));
        }
        mx0 = fmaxf(mx0, __shfl_xor_sync(0xffffffffu, mx0, 1));
        mx0 = fmaxf(mx0, __shfl_xor_sync(0xffffffffu, mx0, 2));
        mx1 = fmaxf(mx1, __shfl_xor_sync(0xffffffffu, mx1, 1));
        mx1 = fmaxf(mx1, __shfl_xor_sync(0xffffffffu, mx1, 2));
        float mn0 = fmaxf(m0, mx0), mn1 = fmaxf(m1, mx1);
        float a0 = ex2f(m0 - mn0), a1 = ex2f(m1 - mn1);
        m0 = mn0; m1 = mn1;
        float rs0 = 0.0f, rs1 = 0.0f;
        #pragma unroll
        for (int j = 0; j < 8; ++j) {
            sf[j][0] = ex2f(sf[j][0] - mn0); rs0 += sf[j][0];
            sf[j][1] = ex2f(sf[j][1] - mn0); rs0 += sf[j][1];
            sf[j][2] = ex2f(sf[j][2] - mn1); rs1 += sf[j][2];
            sf[j][3] = ex2f(sf[j][3] - mn1); rs1 += sf[j][3];
        }
        rs0 += __shfl_xor_sync(0xffffffffu, rs0, 1);
        rs0 += __shfl_xor_sync(0xffffffffu, rs0, 2);
        rs1 += __shfl_xor_sync(0xffffffffu, rs1, 1);
        rs1 += __shfl_xor_sync(0xffffffffu, rs1, 2);
        l0 = l0 * a0 + rs0;
        l1 = l1 * a1 + rs1;
        #pragma unroll
        for (int j = 0; j < 8; ++j) {
            o[j][0] *= a0; o[j][1] *= a0;
            o[j][2] *= a1; o[j][3] *= a1;
        }

        // ---- P fragments (fp16 hi + lo) from S c-frags ----
        uint32_t ph[4][4], pl[4][4];
        #pragma unroll
        for (int t = 0; t < 4; ++t) {
            const int j0 = 2 * t, j1 = 2 * t + 1;
            splitp(sf[j0][0], sf[j0][1], ph[t][0], pl[t][0]);
            splitp(sf[j0][2], sf[j0][3], ph[t][1], pl[t][1]);
            splitp(sf[j1][0], sf[j1][1], ph[t][2], pl[t][2]);
            splitp(sf[j1][2], sf[j1][3], ph[t][3], pl[t][3]);
        }

        // ---- O += P V  (fp16 3-term, V frags via ldmatrix.x4.trans) ----
        #pragma unroll
        for (int t = 0; t < 4; ++t) {
            const int row = t * 16 + brow;
            #pragma unroll
            for (int jp = 0; jp < 4; ++jp) {
                const uint32_t off = (row * FSTR + jp * 16 + lch) * 2;
                uint32_t h0, h1, h2, h3, e0, e1, e2, e3;
                LDSM_X4_T(h0, h1, h2, h3, bV + off);
                LDSM_X4_T(e0, e1, e2, e3, bVl + off);
                mma16816(o[2 * jp],     pl[t], h0, h1);
                mma16816(o[2 * jp],     ph[t], e0, e1);
                mma16816(o[2 * jp],     ph[t], h0, h1);
                mma16816(o[2 * jp + 1], pl[t], h2, h3);
                mma16816(o[2 * jp + 1], ph[t], e2, e3);
                mma16816(o[2 * jp + 1], ph[t], h2, h3);
            }
        }
    }

    // ---- finalize, write ao as fp16 hi/lo [B,N,(H D)] ----
    const int b = bh >> 4;
    const int h = bh & 15;
    const float inv0 = 1.0f / l0, inv1 = 1.0f / l1;
    const int n0 = qi * 128 + wid * 16 + g;
    const int n1 = n0 + 8;
    #pragma unroll
    for (int j = 0; j < 8; ++j) {
        const int d = j * 8 + tig * 2;
        const size_t o0 = (((size_t)b * NN + n0) * HH + h) * DD + d;
        const size_t o1 = (((size_t)b * NN + n1) * HH + h) * DD + d;
        uint32_t hi, lo;
        splitp(o[j][0] * inv0, o[j][1] * inv0, hi, lo);
        *(uint32_t*)(g_aoh + o0) = hi;
        *(uint32_t*)(g_aol + o0) = lo;
        splitp(o[j][2] * inv1, o[j][3] * inv1, hi, lo);
        *(uint32_t*)(g_aoh + o1) = hi;
        *(uint32_t*)(g_aol + o1) = lo;
    }
}

// ===========================================================================
extern "C" void kernel_launch(void* const* d_in, const int* in_sizes, int n_in,
                              void* d_out, int out_size)
{
    const float* x      = (const float*)d_in[0];
    const float* w_qkv  = (const float*)d_in[1];
    const float* w_proj = (const float*)d_in[2];
    const float* b_proj = (const float*)d_in[3];
    const float* ln_w   = (const float*)d_in[4];
    const float* ln_b   = (const float*)d_in[5];
    float* out = (float*)d_out;

    cudaFuncSetAttribute(tc_gemm<0>, cudaFuncAttributeMaxDynamicSharedMemorySize, GEMM_SMEM);
    cudaFuncSetAttribute(tc_gemm<1>, cudaFuncAttributeMaxDynamicSharedMemorySize, GEMM_SMEM);
    cudaFuncSetAttribute(flash_mma, cudaFuncAttributeMaxDynamicSharedMemorySize, FL_SMEM);

    __half *xh, *xl, *wqh, *wql, *wph, *wpl;
    cudaGetSymbolAddress((void**)&xh,  g_xh);  cudaGetSymbolAddress((void**)&xl,  g_xl);
    cudaGetSymbolAddress((void**)&wqh, g_wqh); cudaGetSymbolAddress((void**)&wql, g_wql);
    cudaGetSymbolAddress((void**)&wph, g_wph); cudaGetSymbolAddress((void**)&wpl, g_wpl);

    // 0) pre-split operands to fp16 hi/lo
    f2h_split<<<4096, 256>>>(x,      xh,  xl,  BB*NN*CC/4);
    f2h_split<<<3072, 256>>>(w_qkv,  wqh, wql, CC*3*CC/4);
    f2h_split<<<1024, 256>>>(w_proj, wph, wpl, CC*CC/4);

    // 1) QKV projection -> q/k fp32, v fp16 hi/lo   (256x128 tiles)
    tc_gemm<0><<<dim3(24, 16), 512, GEMM_SMEM>>>(nullptr, nullptr);

    // 2) per-head LayerNorm on q,k -> fp16 hi/lo (q scaled to base-2 domain)
    qk_ln_kernel<<<(2 * BB * HH * NN) / 4, 128>>>(ln_w, ln_b);

    // 3) causal flash attention -> ao fp16 hi/lo
    flash_mma<<<dim3(NN / 128, BB * HH), 256, FL_SMEM>>>();

    // 4) output projection + bias   (256x128 tiles)
    tc_gemm<1><<<dim3(8, 16), 512, GEMM_SMEM>>>(b_proj, out);
}

// round 17
// speedup vs baseline: 1.0293x; 1.0293x over previous
#include <cuda_runtime.h>
#include <cuda_fp16.h>
#include <math.h>
#include <stdint.h>

#define BB 2
#define NN 2048
#define CC 1024
#define HH 16
#define DD 64

// ---- scratch (device globals; allocation-free per harness rules) ----
__device__ float  g_q [BB*HH*NN*DD];          // fp32 q (pre-LN)
__device__ float  g_k [BB*HH*NN*DD];          // fp32 k (pre-LN)
__device__ __half g_qh[BB*HH*NN*DD], g_ql[BB*HH*NN*DD];   // post-LN fp16 hi/lo
__device__ __half g_kh[BB*HH*NN*DD], g_kl[BB*HH*NN*DD];
__device__ __half g_vh[BB*HH*NN*DD], g_vl[BB*HH*NN*DD];
__device__ __half g_aoh[BB*NN*CC],  g_aol[BB*NN*CC];      // attn out hi/lo
__device__ __half g_xh[BB*NN*CC],   g_xl[BB*NN*CC];       // x hi/lo
__device__ __half g_wqh[CC*3*CC],   g_wql[CC*3*CC];       // w_qkv hi/lo
__device__ __half g_wph[CC*CC],     g_wpl[CC*CC];         // w_proj hi/lo

// ===========================================================================
// helpers
// ===========================================================================
__device__ __forceinline__ void mma16816(float* d, const uint32_t* a,
                                         uint32_t b0, uint32_t b1) {
    asm volatile(
        "mma.sync.aligned.m16n8k16.row.col.f32.f16.f16.f32 "
        "{%0,%1,%2,%3}, {%4,%5,%6,%7}, {%8,%9}, {%0,%1,%2,%3};"
        : "+f"(d[0]), "+f"(d[1]), "+f"(d[2]), "+f"(d[3])
        : "r"(a[0]), "r"(a[1]), "r"(a[2]), "r"(a[3]), "r"(b0), "r"(b1));
}
__device__ __forceinline__ uint32_t smem_u32(const void* p) {
    uint32_t a;
    asm("{ .reg .u64 t; cvta.to.shared.u64 t, %1; cvt.u32.u64 %0, t; }"
        : "=r"(a) : "l"(p));
    return a;
}
__device__ __forceinline__ float ex2f(float x) {
    float r;
    asm("ex2.approx.f32 %0, %1;" : "=f"(r) : "f"(x));
    return r;
}
#define LDSM_X4(r0, r1, r2, r3, addr) \
    asm volatile("ldmatrix.sync.aligned.m8n8.x4.shared.b16 " \
                 "{%0,%1,%2,%3}, [%4];" \
                 : "=r"(r0), "=r"(r1), "=r"(r2), "=r"(r3) : "r"(addr))
#define LDSM_X4_T(r0, r1, r2, r3, addr) \
    asm volatile("ldmatrix.sync.aligned.m8n8.x4.trans.shared.b16 " \
                 "{%0,%1,%2,%3}, [%4];" \
                 : "=r"(r0), "=r"(r1), "=r"(r2), "=r"(r3) : "r"(addr))
#define CPA16(dst, src) \
    asm volatile("cp.async.cg.shared.global [%0], [%1], 16;" :: "r"(dst), "l"(src))
#define CPA_COMMIT() asm volatile("cp.async.commit_group;" ::)
#define CPA_WAIT(n)  asm volatile("cp.async.wait_group %0;" :: "n"(n))

// split (a,b) into fp16 hi pair + fp16 residual pair
__device__ __forceinline__ void splitp(float a, float b, uint32_t& hi, uint32_t& lo) {
    __half2 h = __floats2half2_rn(a, b);
    float2 f = __half22float2(h);
    __half2 l = __floats2half2_rn(a - f.x, b - f.y);
    hi = *(uint32_t*)&h;
    lo = *(uint32_t*)&l;
}
__device__ __forceinline__ void split8(float4 v, uint2& hi, uint2& lo) {
    splitp(v.x, v.y, hi.x, lo.x);
    splitp(v.z, v.w, hi.y, lo.y);
}

// ===========================================================================
// fp32 -> fp16 hi/lo streaming conversion
// ===========================================================================
__global__ __launch_bounds__(256)
void f2h_split(const float* __restrict__ src, __half* __restrict__ hi,
               __half* __restrict__ lo, int n4)
{
    int i = blockIdx.x * blockDim.x + threadIdx.x;
    if (i >= n4) return;
    float4 v = ((const float4*)src)[i];
    uint2 h, l;
    split8(v, h, l);
    ((uint2*)hi)[i] = h;
    ((uint2*)lo)[i] = l;
}

// ===========================================================================
// fp16 3-term GEMM: CTA 128x128, 256 threads (2x4 warps, 64x32/warp),
// BK=32, THREE-stage cp.async ring (CPA_WAIT(1): loads get 2 chunk-times),
// one sync per chunk, 96 MMAs per warp between syncs.
// MODE 0: A=x, W=w_qkv (Nn=3072) -> q/k fp32 + v fp16 hi/lo
// MODE 1: A=ao hi/lo, W=w_proj (Nn=1024), +bias -> Cout fp32
// ===========================================================================
#define ASTR 40                        // A smem stride (halves)
#define BSTR 136                       // B smem stride (halves)
#define OAL  (128 * ASTR)              // 5120: A-lo offset (halves)
#define OBH  (2 * 128 * ASTR)          // 10240
#define OBL  (OBH + 32 * BSTR)         // 14592
#define STGH (OBH + 2 * 32 * BSTR)     // 18944 halves / stage
#define STGB (STGH * 2)                // 37888 B
#define GEMM_SMEM (3 * STGB)           // 113664 B (2 CTAs/SM -> 227 KB)

template<int MODE>
__global__ __launch_bounds__(256, 2)
void tc_gemm(const float* __restrict__ bias, float* __restrict__ Cout)
{
    constexpr int K  = 1024;
    constexpr int NC = K / 32;                    // 32 chunks
    constexpr int Nn = (MODE == 0) ? 3072 : 1024;

    const __half* Agh = (MODE == 0) ? g_xh  : g_aoh;
    const __half* Agl = (MODE == 0) ? g_xl  : g_aol;
    const __half* Bgh = (MODE == 0) ? g_wqh : g_wph;
    const __half* Bgl = (MODE == 0) ? g_wql : g_wpl;

    extern __shared__ __half smh[];
    const uint32_t smb = smem_u32(smh);

    const int tid  = threadIdx.x;
    const int wid  = tid >> 5, lane = tid & 31;
    const int wm   = wid & 1,  wn   = wid >> 1;    // 2(m) x 4(n)
    const int g    = lane >> 2, tig = lane & 3;
    const int rowg0 = blockIdx.y * 128;
    const int nblk  = blockIdx.x * 128;

    auto issue = [&](int c, int st) {
        const uint32_t sb = smb + st * STGB;
        #pragma unroll
        for (int s = 0; s < 4; ++s) {             // A: 1024 16B chunks
            int idx = tid + s * 256;
            int arr = idx >> 9, rem = idx & 511;
            int row = rem >> 2, ch = rem & 3;
            const __half* gp = (arr ? Agl : Agh)
                + (size_t)(rowg0 + row) * K + c * 32 + ch * 8;
            CPA16(sb + ((arr ? OAL : 0) + row * ASTR + ch * 8) * 2, gp);
        }
        #pragma unroll
        for (int s = 0; s < 4; ++s) {             // B: 1024 16B chunks
            int idx = tid + s * 256;
            int arr = idx >> 9, rem = idx & 511;
            int rr = rem >> 4, ch = rem & 15;
            const __half* gp = (arr ? Bgl : Bgh)
                + (size_t)(c * 32 + rr) * Nn + nblk + ch * 8;
            CPA16(sb + ((arr ? OBL : OBH) + rr * BSTR + ch * 8) * 2, gp);
        }
    };

    float acc[4][4][4];
    #pragma unroll
    for (int i = 0; i < 4; ++i)
        #pragma unroll
        for (int j = 0; j < 4; ++j)
            #pragma unroll
            for (int r = 0; r < 4; ++r) acc[i][j][r] = 0.0f;

    issue(0, 0); CPA_COMMIT();
    issue(1, 1); CPA_COMMIT();

    const int lrow = lane & 15, lch = (lane >> 4) << 3;
    const int brow = ((lane >> 3) & 1) * 8 + (lane & 7);

    int st = 0;
    for (int c = 0; c < NC; ++c) {
        CPA_WAIT(1);                     // chunk c complete (c+1 may be in flight)
        __syncthreads();                 // stage (c+2)%3's readers (iter c-1) done
        if (c + 2 < NC) {
            int nst = st + 2; if (nst >= 3) nst -= 3;
            issue(c + 2, nst);
        }
        CPA_COMMIT();                    // always: keeps group accounting exact

        const __half* Ah = smh + st * STGH;
        const __half* Al = Ah + OAL;
        const __half* Bh = smh + st * STGH + OBH;
        const __half* Bl = smh + st * STGH + OBL;

        #pragma unroll
        for (int ks = 0; ks < 2; ++ks) {
            uint32_t afh[4][4], afl[4][4], bfh[4][2], bfl[4][2];
            #pragma unroll
            for (int s = 0; s < 4; ++s) {
                const int m0 = wm * 64 + s * 16;
                LDSM_X4(afh[s][0], afh[s][1], afh[s][2], afh[s][3],
                        smem_u32(Ah + (m0 + lrow) * ASTR + ks * 16 + lch));
                LDSM_X4(afl[s][0], afl[s][1], afl[s][2], afl[s][3],
                        smem_u32(Al + (m0 + lrow) * ASTR + ks * 16 + lch));
            }
            #pragma unroll
            for (int np = 0; np < 2; ++np) {
                const int n0 = wn * 32 + np * 16;
                LDSM_X4_T(bfh[2*np][0], bfh[2*np][1], bfh[2*np+1][0], bfh[2*np+1][1],
                          smem_u32(Bh + (ks * 16 + brow) * BSTR + n0 + lch));
                LDSM_X4_T(bfl[2*np][0], bfl[2*np][1], bfl[2*np+1][0], bfl[2*np+1][1],
                          smem_u32(Bl + (ks * 16 + brow) * BSTR + n0 + lch));
            }
            #pragma unroll
            for (int i = 0; i < 4; ++i)
                #pragma unroll
                for (int j = 0; j < 4; ++j) {
                    mma16816(acc[i][j], afl[i], bfh[j][0], bfh[j][1]);
                    mma16816(acc[i][j], afh[i], bfl[j][0], bfl[j][1]);
                    mma16816(acc[i][j], afh[i], bfh[j][0], bfh[j][1]);
                }
        }
        if (++st >= 3) st = 0;
    }

    // ---- epilogue ----
    #pragma unroll
    for (int i = 0; i < 4; ++i) {
        const int r1 = rowg0 + wm * 64 + i * 16 + g;
        #pragma unroll
        for (int j = 0; j < 4; ++j) {
            const int cgl = nblk + wn * 32 + j * 8 + tig * 2;
            if (MODE == 0) {
                const int which = cgl >> 10;
                const int head  = (cgl >> 6) & 15;
                const int dd    = cgl & 63;
                #pragma unroll
                for (int h2 = 0; h2 < 2; ++h2) {
                    const int r = r1 + h2 * 8;
                    const int b = r >> 11, n = r & 2047;
                    const size_t off = ((size_t)(b * HH + head) * NN + n) * DD + dd;
                    float a0 = acc[i][j][h2 * 2], a1 = acc[i][j][h2 * 2 + 1];
                    if (which == 0)      *(float2*)(g_q + off) = make_float2(a0, a1);
                    else if (which == 1) *(float2*)(g_k + off) = make_float2(a0, a1);
                    else {
                        uint32_t hi, lo;
                        splitp(a0, a1, hi, lo);
                        *(uint32_t*)(g_vh + off) = hi;
                        *(uint32_t*)(g_vl + off) = lo;
                    }
                }
            } else {
                const float2 bv = *(const float2*)(bias + cgl);
                #pragma unroll
                for (int h2 = 0; h2 < 2; ++h2) {
                    const int r = r1 + h2 * 8;
                    *(float2*)(Cout + (size_t)r * Nn + cgl) =
                        make_float2(acc[i][j][h2 * 2] + bv.x,
                                    acc[i][j][h2 * 2 + 1] + bv.y);
                }
            }
        }
    }
}

// ===========================================================================
// Per-head LayerNorm (D=64) on q,k.  q additionally scaled by sqrt(D)*log2(e)
// so flash softmax can use raw ex2 (base-2 domain).  fp16 hi/lo output.
// ===========================================================================
#define QSCALE 11.5415603271117f       // 8 * log2(e)

__global__ __launch_bounds__(128)
void qk_ln_kernel(const float* __restrict__ ln_w, const float* __restrict__ ln_b)
{
    const int R = BB * HH * NN;
    int row  = blockIdx.x * 4 + (threadIdx.x >> 5);
    int lane = threadIdx.x & 31;

    const bool isq = (row < R);
    const float* src = isq ? g_q : g_k;
    __half* dh = isq ? g_qh : g_kh;
    __half* dl = isq ? g_ql : g_kl;
    float extra = isq ? QSCALE : 1.0f;
    int r = isq ? row : (row - R);

    const float* p = src + (size_t)r * DD;
    float x0 = p[lane];
    float x1 = p[lane + 32];
    float s  = x0 + x1;
    float ss = x0 * x0 + x1 * x1;
    #pragma unroll
    for (int o = 16; o > 0; o >>= 1) {
        s  += __shfl_xor_sync(0xffffffffu, s,  o);
        ss += __shfl_xor_sync(0xffffffffu, ss, o);
    }
    float mu  = s * (1.0f / 64.0f);
    float var = ss * (1.0f / 64.0f) - mu * mu;
    float inv = rsqrtf(var + 1e-5f);
    float y0 = ((x0 - mu) * inv * ln_w[lane]      + ln_b[lane])      * extra;
    float y1 = ((x1 - mu) * inv * ln_w[lane + 32] + ln_b[lane + 32]) * extra;

    __half h0 = __float2half_rn(y0);
    __half h1 = __float2half_rn(y1);
    size_t off = (size_t)r * DD + lane;
    dh[off]      = h0;
    dh[off + 32] = h1;
    dl[off]      = __float2half_rn(y0 - __half2float(h0));
    dl[off + 32] = __float2half_rn(y1 - __half2float(h1));
}

// ===========================================================================
// Tensor-core causal flash attention, pre-split fp16, cp.async double-buffer,
// ONE sync per key tile, base-2 softmax (single ex2.approx per score).
// CTA: 128 q-rows; 8 warps x 16 rows; key tile 64.
// ===========================================================================
#define FSTR 72                         // smem row stride (halves)
#define ARRB (64 * FSTR * 2)            // 9216 B per array
#define BUFB (4 * ARRB)                 // 36864 B per KV buffer
#define FL_SMEM (2 * BUFB)              // 73728 B

__global__ __launch_bounds__(256)
void flash_mma()
{
    extern __shared__ __align__(1024) char fsm[];
    const uint32_t fsmb = smem_u32(fsm);

    const int bh  = blockIdx.y;
    const int qi  = (gridDim.x - 1) - blockIdx.x;   // heavy tiles first
    const int tid = threadIdx.x;
    const int wid = tid >> 5, lane = tid & 31;
    const int g   = lane >> 2, tig = lane & 3;

    const size_t hb = (size_t)bh * NN * DD;
    const size_t qb = hb + (size_t)qi * 128 * DD;

    // ---- stage Q hi/lo into smem, extract per-warp a-frags ----
    {
        __half* Qh = (__half*)fsm;
        __half* Ql = (__half*)(fsm + 18432);
        #pragma unroll
        for (int s = 0; s < 4; ++s) {
            int idx = tid + s * 256;
            int row = idx >> 3, ch = idx & 7;
            *(uint4*)&Qh[row * FSTR + ch * 8] = *(const uint4*)(g_qh + qb + row * 64 + ch * 8);
            *(uint4*)&Ql[row * FSTR + ch * 8] = *(const uint4*)(g_ql + qb + row * 64 + ch * 8);
        }
    }
    __syncthreads();

    uint32_t qh[4][4], ql[4][4];
    {
        const int lr = lane & 15, lc = (lane >> 4) << 3;
        #pragma unroll
        for (int kk = 0; kk < 4; ++kk) {
            uint32_t a = fsmb + ((wid * 16 + lr) * FSTR + kk * 16 + lc) * 2;
            LDSM_X4(qh[kk][0], qh[kk][1], qh[kk][2], qh[kk][3], a);
            LDSM_X4(ql[kk][0], ql[kk][1], ql[kk][2], ql[kk][3], a + 18432);
        }
    }
    __syncthreads();

    auto issueKV = [&](int kj, int b) {
        const size_t kb = hb + (size_t)kj * 64 * DD;
        const uint32_t sb = fsmb + b * BUFB;
        const __half* gs[4] = { g_kh + kb, g_kl + kb, g_vh + kb, g_vl + kb };
        #pragma unroll
        for (int a = 0; a < 4; ++a) {
            const uint32_t so = sb + a * ARRB;
            #pragma unroll
            for (int s = 0; s < 2; ++s) {
                int idx = tid + s * 256;
                int row = idx >> 3, ch = idx & 7;
                CPA16(so + (row * FSTR + ch * 8) * 2, gs[a] + row * 64 + ch * 8);
            }
        }
    };

    float m0 = -1e30f, m1 = -1e30f, l0 = 0.0f, l1 = 0.0f;
    float o[8][4];
    #pragma unroll
    for (int j = 0; j < 8; ++j)
        #pragma unroll
        for (int r = 0; r < 4; ++r) o[j][r] = 0.0f;

    const int lrow = lane & 15, lch = (lane >> 4) << 3;
    const int brow = ((lane >> 3) & 1) * 8 + (lane & 7);
    const int kend = 2 * qi + 1;

    issueKV(0, 0);
    CPA_COMMIT();

    for (int kj = 0; kj <= kend; ++kj) {
        CPA_WAIT(0);
        __syncthreads();                 // tile kj ready; opposite buffer free
        if (kj < kend) {
            issueKV(kj + 1, (kj + 1) & 1);
            CPA_COMMIT();
        }

        const uint32_t bK  = fsmb + (kj & 1) * BUFB;           // K hi
        const uint32_t bKl = bK + ARRB;                        // K lo
        const uint32_t bV  = bK + 2 * ARRB;                    // V hi
        const uint32_t bVl = bK + 3 * ARRB;                    // V lo

        // ---- S = Q K^T (fp16 3-term, non-trans b-frags); base-2 domain ----
        float sf[8][4];
        #pragma unroll
        for (int j = 0; j < 8; ++j)
            #pragma unroll
            for (int r = 0; r < 4; ++r) sf[j][r] = 0.0f;

        #pragma unroll
        for (int kk = 0; kk < 4; ++kk) {
            #pragma unroll
            for (int jp = 0; jp < 4; ++jp) {
                const uint32_t off = ((jp * 16 + lrow) * FSTR + kk * 16 + lch) * 2;
                uint32_t h0, h1, h2, h3, e0, e1, e2, e3;
                LDSM_X4(h0, h1, h2, h3, bK + off);
                LDSM_X4(e0, e1, e2, e3, bKl + off);
                mma16816(sf[2*jp],   ql[kk], h0, h2);
                mma16816(sf[2*jp],   qh[kk], e0, e2);
                mma16816(sf[2*jp],   qh[kk], h0, h2);
                mma16816(sf[2*jp+1], ql[kk], h1, h3);
                mma16816(sf[2*jp+1], qh[kk], e1, e3);
                mma16816(sf[2*jp+1], qh[kk], h1, h3);
            }
        }

        // ---- causal mask on diagonal tiles ----
        if (kj >= 2 * qi) {
            const int row0 = qi * 128 + wid * 16 + g;
            const int row1 = row0 + 8;
            #pragma unroll
            for (int j = 0; j < 8; ++j) {
                const int c0 = kj * 64 + j * 8 + tig * 2;
                if (row0 < c0)     sf[j][0] = -1e30f;
                if (row0 < c0 + 1) sf[j][1] = -1e30f;
                if (row1 < c0)     sf[j][2] = -1e30f;
                if (row1 < c0 + 1) sf[j][3] = -1e30f;
            }
        }

        // ---- online softmax, base-2 (rows g, g+8; quad-replicated) ----
        float mx0 = -1e30f, mx1 = -1e30f;
        #pragma unroll
        for (int j = 0; j < 8; ++j) {
            mx0 = fmaxf(mx0, fmaxf(sf[j][0], sf[j][1]));
            mx1 = fmaxf(mx1, fmaxf(sf[j][2], sf[j][3]));
        }
        mx0 = fmaxf(mx0, __shfl_xor_sync(0xffffffffu, mx0, 1));
        mx0 = fmaxf(mx0, __shfl_xor_sync(0xffffffffu, mx0, 2));
        mx1 = fmaxf(mx1, __shfl_xor_sync(0xffffffffu, mx1, 1));
        mx1 = fmaxf(mx1, __shfl_xor_sync(0xffffffffu, mx1, 2));
        float mn0 = fmaxf(m0, mx0), mn1 = fmaxf(m1, mx1);
        float a0 = ex2f(m0 - mn0), a1 = ex2f(m1 - mn1);
        m0 = mn0; m1 = mn1;
        float rs0 = 0.0f, rs1 = 0.0f;
        #pragma unroll
        for (int j = 0; j < 8; ++j) {
            sf[j][0] = ex2f(sf[j][0] - mn0); rs0 += sf[j][0];
            sf[j][1] = ex2f(sf[j][1] - mn0); rs0 += sf[j][1];
            sf[j][2] = ex2f(sf[j][2] - mn1); rs1 += sf[j][2];
            sf[j][3] = ex2f(sf[j][3] - mn1); rs1 += sf[j][3];
        }
        rs0 += __shfl_xor_sync(0xffffffffu, rs0, 1);
        rs0 += __shfl_xor_sync(0xffffffffu, rs0, 2);
        rs1 += __shfl_xor_sync(0xffffffffu, rs1, 1);
        rs1 += __shfl_xor_sync(0xffffffffu, rs1, 2);
        l0 = l0 * a0 + rs0;
        l1 = l1 * a1 + rs1;
        #pragma unroll
        for (int j = 0; j < 8; ++j) {
            o[j][0] *= a0; o[j][1] *= a0;
            o[j][2] *= a1; o[j][3] *= a1;
        }

        // ---- P fragments (fp16 hi + lo) from S c-frags ----
        uint32_t ph[4][4], pl[4][4];
        #pragma unroll
        for (int t = 0; t < 4; ++t) {
            const int j0 = 2 * t, j1 = 2 * t + 1;
            splitp(sf[j0][0], sf[j0][1], ph[t][0], pl[t][0]);
            splitp(sf[j0][2], sf[j0][3], ph[t][1], pl[t][1]);
            splitp(sf[j1][0], sf[j1][1], ph[t][2], pl[t][2]);
            splitp(sf[j1][2], sf[j1][3], ph[t][3], pl[t][3]);
        }

        // ---- O += P V  (fp16 3-term, V frags via ldmatrix.x4.trans) ----
        #pragma unroll
        for (int t = 0; t < 4; ++t) {
            const int row = t * 16 + brow;
            #pragma unroll
            for (int jp = 0; jp < 4; ++jp) {
                const uint32_t off = (row * FSTR + jp * 16 + lch) * 2;
                uint32_t h0, h1, h2, h3, e0, e1, e2, e3;
                LDSM_X4_T(h0, h1, h2, h3, bV + off);
                LDSM_X4_T(e0, e1, e2, e3, bVl + off);
                mma16816(o[2 * jp],     pl[t], h0, h1);
                mma16816(o[2 * jp],     ph[t], e0, e1);
                mma16816(o[2 * jp],     ph[t], h0, h1);
                mma16816(o[2 * jp + 1], pl[t], h2, h3);
                mma16816(o[2 * jp + 1], ph[t], e2, e3);
                mma16816(o[2 * jp + 1], ph[t], h2, h3);
            }
        }
    }

    // ---- finalize, write ao as fp16 hi/lo [B,N,(H D)] ----
    const int b = bh >> 4;
    const int h = bh & 15;
    const float inv0 = 1.0f / l0, inv1 = 1.0f / l1;
    const int n0 = qi * 128 + wid * 16 + g;
    const int n1 = n0 + 8;
    #pragma unroll
    for (int j = 0; j < 8; ++j) {
        const int d = j * 8 + tig * 2;
        const size_t o0 = (((size_t)b * NN + n0) * HH + h) * DD + d;
        const size_t o1 = (((size_t)b * NN + n1) * HH + h) * DD + d;
        uint32_t hi, lo;
        splitp(o[j][0] * inv0, o[j][1] * inv0, hi, lo);
        *(uint32_t*)(g_aoh + o0) = hi;
        *(uint32_t*)(g_aol + o0) = lo;
        splitp(o[j][2] * inv1, o[j][3] * inv1, hi, lo);
        *(uint32_t*)(g_aoh + o1) = hi;
        *(uint32_t*)(g_aol + o1) = lo;
    }
}

// ===========================================================================
extern "C" void kernel_launch(void* const* d_in, const int* in_sizes, int n_in,
                              void* d_out, int out_size)
{
    const float* x      = (const float*)d_in[0];
    const float* w_qkv  = (const float*)d_in[1];
    const float* w_proj = (const float*)d_in[2];
    const float* b_proj = (const float*)d_in[3];
    const float* ln_w   = (const float*)d_in[4];
    const float* ln_b   = (const float*)d_in[5];
    float* out = (float*)d_out;

    cudaFuncSetAttribute(tc_gemm<0>, cudaFuncAttributeMaxDynamicSharedMemorySize, GEMM_SMEM);
    cudaFuncSetAttribute(tc_gemm<1>, cudaFuncAttributeMaxDynamicSharedMemorySize, GEMM_SMEM);
    cudaFuncSetAttribute(flash_mma, cudaFuncAttributeMaxDynamicSharedMemorySize, FL_SMEM);

    __half *xh, *xl, *wqh, *wql, *wph, *wpl;
    cudaGetSymbolAddress((void**)&xh,  g_xh);  cudaGetSymbolAddress((void**)&xl,  g_xl);
    cudaGetSymbolAddress((void**)&wqh, g_wqh); cudaGetSymbolAddress((void**)&wql, g_wql);
    cudaGetSymbolAddress((void**)&wph, g_wph); cudaGetSymbolAddress((void**)&wpl, g_wpl);

    // 0) pre-split operands to fp16 hi/lo
    f2h_split<<<4096, 256>>>(x,      xh,  xl,  BB*NN*CC/4);
    f2h_split<<<3072, 256>>>(w_qkv,  wqh, wql, CC*3*CC/4);
    f2h_split<<<1024, 256>>>(w_proj, wph, wpl, CC*CC/4);

    // 1) QKV projection -> q/k fp32, v fp16 hi/lo   (128x128 tiles, 3-stage)
    tc_gemm<0><<<dim3(24, 32), 256, GEMM_SMEM>>>(nullptr, nullptr);

    // 2) per-head LayerNorm on q,k -> fp16 hi/lo (q scaled to base-2 domain)
    qk_ln_kernel<<<(2 * BB * HH * NN) / 4, 128>>>(ln_w, ln_b);

    // 3) causal flash attention -> ao fp16 hi/lo
    flash_mma<<<dim3(NN / 128, BB * HH), 256, FL_SMEM>>>();

    // 4) output projection + bias
    tc_gemm<1><<<dim3(8, 32), 256, GEMM_SMEM>>>(b_proj, out);
}